// round 15
// baseline (speedup 1.0000x reference)
#include <cuda_runtime.h>
#include <cuda_fp16.h>
#include <math.h>
#include <stdint.h>

#define NN 100000
#define EE 1600000
#define DIN 128
#define DH  256
#define NT1 782                      // tiles covering rows 0..100095
#define NT_ALL 1563                  // tiles covering rows 0..200063

// ---- device scratch (allocation-free contract) ----
__device__ uint4  g_xh[(size_t)NN * 32];        // interleaved fp16 x|x_tilde [N][256]h (51.2MB)
__device__ __half g_agg16[2ull * NN * DIN];     // fp16 agg (51.2MB)
__device__ __half g_h16[(size_t)NT1 * 32768];   // fp16 h, fragment-native blocks (51.2MB)
__device__ __half g_W1h[DH * DIN];              // fp16 W1 [256][128] K-major
__device__ float  g_colsum[DH];
__device__ int    g_rowptr[NN + 1];
__device__ int    g_bar;

// ================= helpers =================
__device__ __forceinline__ uint32_t smem_u32(const void* p) {
    uint32_t a;
    asm("{ .reg .u64 t; cvta.to.shared.u64 t, %1; cvt.u32.u64 %0, t; }" : "=r"(a) : "l"(p));
    return a;
}
__device__ __forceinline__ void ldsm_x4(uint32_t& r0, uint32_t& r1, uint32_t& r2, uint32_t& r3,
                                        uint32_t addr) {
    asm volatile("ldmatrix.sync.aligned.m8n8.x4.shared.b16 {%0,%1,%2,%3}, [%4];"
                 : "=r"(r0), "=r"(r1), "=r"(r2), "=r"(r3) : "r"(addr));
}
__device__ __forceinline__ void mma16816(float* d, const uint32_t* a, const uint32_t* b) {
    asm volatile("mma.sync.aligned.m16n8k16.row.col.f32.f16.f16.f32 "
                 "{%0,%1,%2,%3}, {%4,%5,%6,%7}, {%8,%9}, {%0,%1,%2,%3};"
                 : "+f"(d[0]), "+f"(d[1]), "+f"(d[2]), "+f"(d[3])
                 : "r"(a[0]), "r"(a[1]), "r"(a[2]), "r"(a[3]), "r"(b[0]), "r"(b[1]));
}
__device__ __forceinline__ void cp_async16(uint32_t saddr, const void* gptr, int src_bytes) {
    uint64_t ga;
    asm("cvta.to.global.u64 %0, %1;" : "=l"(ga) : "l"(gptr));
    asm volatile("cp.async.cg.shared.global [%0], [%1], 16, %2;"
                 :: "r"(saddr), "l"(ga), "r"(src_bytes));
}
__device__ __forceinline__ void cp_commit() {
    asm volatile("cp.async.commit_group;");
}
__device__ __forceinline__ void stg_cs_v4(void* gptr, uint4 v) {
    asm volatile("st.global.cs.v4.b32 [%0], {%1, %2, %3, %4};"
                 :: "l"(gptr), "r"(v.x), "r"(v.y), "r"(v.z), "r"(v.w) : "memory");
}

// ================= fused prep: rowptr | cvt | cvtW+init =================
#define ROW_BLOCKS 6250
#define CVT_BLOCKS 12500
__global__ void k_prep(const float4* __restrict__ x4, const float4* __restrict__ xt4,
                       const int* __restrict__ adj_row, const float* __restrict__ W1) {
    int b = blockIdx.x, t = threadIdx.x;
    if (b < ROW_BLOCKS) {
        int e = b * 256 + t;
        if (e >= EE) return;
        int r  = adj_row[e];
        int rp = (e == 0) ? -1 : adj_row[e - 1];
        for (int k = rp + 1; k <= r; k++) g_rowptr[k] = e;
        if (e == EE - 1)
            for (int k = r + 1; k <= NN; k++) g_rowptr[k] = EE;
    } else if (b < ROW_BLOCKS + CVT_BLOCKS) {
        int i = (b - ROW_BLOCKS) * 256 + t;
        if (i >= NN * 32) return;
        int row = i >> 5, j = i & 31;
        const float4* src = (j < 16) ? x4 : xt4;
        int jj = j & 15;
        float4 a = src[(size_t)row * 32 + jj * 2];
        float4 c = src[(size_t)row * 32 + jj * 2 + 1];
        __half2 h0 = __floats2half2_rn(a.x, a.y);
        __half2 h1 = __floats2half2_rn(a.z, a.w);
        __half2 h2 = __floats2half2_rn(c.x, c.y);
        __half2 h3 = __floats2half2_rn(c.z, c.w);
        uint4 o;
        o.x = *(unsigned*)&h0; o.y = *(unsigned*)&h1;
        o.z = *(unsigned*)&h2; o.w = *(unsigned*)&h3;
        g_xh[(size_t)row * 32 + j] = o;
    } else {
        int wb = b - ROW_BLOCKS - CVT_BLOCKS;
        int i = wb * 256 + t;
        if (i < DH * DIN) g_W1h[i] = __float2half_rn(W1[i]);
        if (wb == 0) {
            g_colsum[t] = 0.0f;
            if (t == 0) g_bar = 0;
        }
    }
}

// ================= SpMM (fp16 gather, fp16 agg out, streaming stores) =================
__global__ void k_spmm(const float* __restrict__ vals, const int* __restrict__ cols) {
    int w    = (blockIdx.x * blockDim.x + threadIdx.x) >> 5;
    int lane = threadIdx.x & 31;
    if (w >= NN) return;
    int e0 = g_rowptr[w], e1 = g_rowptr[w + 1];
    float a0 = 0.f, a1 = 0.f, a2 = 0.f, a3 = 0.f, a4 = 0.f, a5 = 0.f, a6 = 0.f, a7 = 0.f;
#pragma unroll 4
    for (int e = e0; e < e1; e++) {
        float wt = __ldg(vals + e);
        int   c  = __ldg(cols + e);
        uint4 u  = g_xh[(size_t)c * 32 + lane];
        float2 f0 = __half22float2(*(const __half2*)&u.x);
        float2 f1 = __half22float2(*(const __half2*)&u.y);
        float2 f2 = __half22float2(*(const __half2*)&u.z);
        float2 f3 = __half22float2(*(const __half2*)&u.w);
        a0 += wt * f0.x; a1 += wt * f0.y;
        a2 += wt * f1.x; a3 += wt * f1.y;
        a4 += wt * f2.x; a5 += wt * f2.y;
        a6 += wt * f3.x; a7 += wt * f3.y;
    }
    size_t base = (lane < 16) ? (size_t)w : (size_t)NN + w;
    int j = lane & 15;
    __half2 h0 = __floats2half2_rn(a0, a1);
    __half2 h1 = __floats2half2_rn(a2, a3);
    __half2 h2 = __floats2half2_rn(a4, a5);
    __half2 h3 = __floats2half2_rn(a6, a7);
    uint4 o;
    o.x = *(unsigned*)&h0; o.y = *(unsigned*)&h1;
    o.z = *(unsigned*)&h2; o.w = *(unsigned*)&h3;
    stg_cs_v4((uint4*)g_agg16 + base * 16 + j, o);
}

// ================= single persistent GEMM kernel =================
// 512 thr = 16 warps (2x8), warp tile 64x32.
// PASS1 (fp32 acc): tiles 0..NT1-1 -> h (fragment-native) + colsum(rows<NN).
// Barrier. s,v. PHASE2A: matvec over stored h. PHASE2B: GEMM for tiles NT1..NT_ALL-1.
#define LDA 136
#define LDB 136
#define ASZ (128 * LDA)
#define SM_HALVES (2 * ASZ + 256 * LDB)
#define LDO 132
#define SM_BYTES (SM_HALVES * 2 + 2 * 8 * LDO * 4 + 2048)
#define GRID_GEMM 148

__global__ void __launch_bounds__(512, 1) k_gemm_all(const float* __restrict__ prelu_a,
                                                     const float* __restrict__ w_bil,
                                                     float* __restrict__ out) {
    extern __shared__ __half smem[];
    __half* Ab[2] = { smem, smem + ASZ };
    __half* Bs = smem + 2 * ASZ;                  // [256][LDB]
    float* ostg0 = (float*)(smem + SM_HALVES);    // [8][LDO] x 2
    float* sv   = ostg0 + 2 * 8 * LDO;            // s[256] then v[256]
    int tid = threadIdx.x, lane = tid & 31, wid = tid >> 5;
    int warp_m = wid >> 3, warp_n = wid & 7;      // 2 x 8
    const long totalRows = 2L * NN;

    // ---- load B (all of W1h) once ----
    {
        const uint4* bsrc = (const uint4*)g_W1h;
#pragma unroll
        for (int i = 0; i < 8; i++) {
            int c = tid + i * 512;
            int row = c >> 4, k4 = c & 15;
            *(uint4*)(Bs + row * LDB + k4 * 8) = bsrc[row * 16 + k4];
        }
    }

    auto prefetchA = [&](long tile, __half* dst) {
        const uint4* asrc = (const uint4*)g_agg16;
        long rb = tile * 128;
#pragma unroll
        for (int i = 0; i < 4; i++) {
            int c = tid + i * 512;
            int row = c >> 4, k4 = c & 15;
            long grow = rb + row;
            int ok = (grow < totalRows) ? 16 : 0;
            long src = ok ? grow : 0;
            cp_async16(smem_u32(dst + row * LDA + k4 * 8), asrc + src * 16 + k4, ok);
        }
        cp_commit();
    };

    float pa = prelu_a[0];
    int r4 = lane >> 2, c4 = (lane & 3) * 2;
    int aRow = warp_m * 64 + (lane & 15);
    int aCol = (lane >> 4) * 8;
    int bGrp = lane >> 3;
    int bRowOff = ((bGrp >> 1) * 8) + (lane & 7);
    int bKadd = (bGrp & 1) * 8;

    // ================== PASS 1: fp32 GEMM -> h store + colsum ==================
    {
        float csum[8];
#pragma unroll
        for (int q = 0; q < 8; q++) csum[q] = 0.f;
        int p = 0;
        long tile = blockIdx.x;
        if (tile < NT1) prefetchA(tile, Ab[0]);
        for (; tile < NT1; tile += GRID_GEMM) {
            long next = tile + GRID_GEMM;
            if (next < NT1) {
                prefetchA(next, Ab[p ^ 1]);
                asm volatile("cp.async.wait_group 1;");
            } else {
                asm volatile("cp.async.wait_group 0;");
            }
            __syncthreads();

            __half* As = Ab[p];
            float acc[4][4][4];
#pragma unroll
            for (int mt = 0; mt < 4; mt++)
#pragma unroll
                for (int nt = 0; nt < 4; nt++)
#pragma unroll
                    for (int q = 0; q < 4; q++) acc[mt][nt][q] = 0.f;

#pragma unroll
            for (int ks = 0; ks < 8; ks++) {
                uint32_t a[4][4];
#pragma unroll
                for (int mt = 0; mt < 4; mt++) {
                    uint32_t addr = smem_u32(As + (aRow + mt * 16) * LDA + ks * 16 + aCol);
                    ldsm_x4(a[mt][0], a[mt][1], a[mt][2], a[mt][3], addr);
                }
                uint32_t b[4][2];
#pragma unroll
                for (int np = 0; np < 2; np++) {
                    uint32_t addr = smem_u32(Bs + (warp_n * 32 + np * 16 + bRowOff) * LDB + ks * 16 + bKadd);
                    uint32_t r0, r1, r2, r3;
                    ldsm_x4(r0, r1, r2, r3, addr);
                    b[np * 2][0] = r0; b[np * 2][1] = r1;
                    b[np * 2 + 1][0] = r2; b[np * 2 + 1][1] = r3;
                }
#pragma unroll
                for (int mt = 0; mt < 4; mt++)
#pragma unroll
                    for (int nt = 0; nt < 4; nt++)
                        mma16816(acc[mt][nt], a[mt], b[nt]);
            }

            long rowBase = tile * 128;
            uint4* hdst = (uint4*)g_h16 + tile * 4096 + wid * 256 + lane * 8;
#pragma unroll
            for (int mt = 0; mt < 4; mt++) {
                long r_lo = rowBase + warp_m * 64 + mt * 16 + r4;
                bool p_lo = r_lo < NN, p_hi = (r_lo + 8) < NN;
                uint32_t pk[4][2];
#pragma unroll
                for (int nt = 0; nt < 4; nt++) {
                    float* d = acc[mt][nt];
                    float z0 = (d[0] >= 0.f) ? d[0] : pa * d[0];
                    float z1 = (d[1] >= 0.f) ? d[1] : pa * d[1];
                    float z2 = (d[2] >= 0.f) ? d[2] : pa * d[2];
                    float z3 = (d[3] >= 0.f) ? d[3] : pa * d[3];
                    if (p_lo) { csum[nt * 2] += z0; csum[nt * 2 + 1] += z1; }
                    if (p_hi) { csum[nt * 2] += z2; csum[nt * 2 + 1] += z3; }
                    __half2 ha = __floats2half2_rn(z0, z1);
                    __half2 hb = __floats2half2_rn(z2, z3);
                    pk[nt][0] = *(uint32_t*)&ha;
                    pk[nt][1] = *(uint32_t*)&hb;
                }
                hdst[mt * 2]     = make_uint4(pk[0][0], pk[0][1], pk[1][0], pk[1][1]);
                hdst[mt * 2 + 1] = make_uint4(pk[2][0], pk[2][1], pk[3][0], pk[3][1]);
            }
            __syncthreads();
            p ^= 1;
        }
#pragma unroll
        for (int o = 4; o <= 16; o <<= 1)
#pragma unroll
            for (int q = 0; q < 8; q++)
                csum[q] += __shfl_xor_sync(0xffffffffu, csum[q], o);
        if (lane < 4) {
#pragma unroll
            for (int q = 0; q < 8; q++)
                atomicAdd(&g_colsum[warp_n * 32 + (q >> 1) * 8 + lane * 2 + (q & 1)], csum[q]);
        }
    }

    // ================== grid-wide barrier ==================
    __threadfence();
    __syncthreads();
    if (tid == 0) {
        atomicAdd(&g_bar, 1);
        while (*(volatile int*)&g_bar < GRID_GEMM) { }
    }
    __syncthreads();
    __threadfence();

    // ================== s = sigmoid(colsum/N), v = w_bil @ s ==================
    {
        if (NT1 + blockIdx.x < NT_ALL) prefetchA(NT1 + blockIdx.x, Ab[0]);  // overlap
        if (tid < 256) {
            float m = g_colsum[tid] / (float)NN;
            sv[tid] = 1.f / (1.f + expf(-m));
        }
        __syncthreads();
        int j0 = wid * 16;
#pragma unroll 2
        for (int jj = 0; jj < 16; jj++) {
            int j = j0 + jj;
            float a = 0.f;
#pragma unroll
            for (int u = 0; u < 8; u++)
                a += __ldg(&w_bil[j * DH + lane + u * 32]) * sv[lane + u * 32];
#pragma unroll
            for (int o = 16; o > 0; o >>= 1) a += __shfl_xor_sync(0xffffffffu, a, o);
            if (lane == 0) sv[DH + j] = a;
        }
        __syncthreads();
    }
    float* v = sv + DH;

    // ================== PHASE 2A: matvec over stored h (tiles 0..NT1-1) ==================
    {
        int task = blockIdx.x * 16 + wid;          // 2*NT1 = 1564 tasks
        if (task < 2 * NT1) {
            int tile = task >> 1, wm = task & 1;
            float rsum[8];
#pragma unroll
            for (int q = 0; q < 8; q++) rsum[q] = 0.f;
            const uint4* hsrc = (const uint4*)g_h16 + (size_t)tile * 4096 + lane * 8;
#pragma unroll 2
            for (int wn = 0; wn < 8; wn++) {
                const uint4* blk = hsrc + (wm * 8 + wn) * 256;
#pragma unroll
                for (int mt = 0; mt < 4; mt++) {
                    uint4 ua = blk[mt * 2];
                    uint4 ub = blk[mt * 2 + 1];
                    float vv0 = v[wn * 32 + 0 * 8 + c4], vv1 = v[wn * 32 + 0 * 8 + c4 + 1];
                    float2 f;
                    f = __half22float2(*(const __half2*)&ua.x);
                    rsum[mt * 2]     += f.x * vv0 + f.y * vv1;
                    f = __half22float2(*(const __half2*)&ua.y);
                    rsum[mt * 2 + 1] += f.x * vv0 + f.y * vv1;
                    vv0 = v[wn * 32 + 1 * 8 + c4]; vv1 = v[wn * 32 + 1 * 8 + c4 + 1];
                    f = __half22float2(*(const __half2*)&ua.z);
                    rsum[mt * 2]     += f.x * vv0 + f.y * vv1;
                    f = __half22float2(*(const __half2*)&ua.w);
                    rsum[mt * 2 + 1] += f.x * vv0 + f.y * vv1;
                    vv0 = v[wn * 32 + 2 * 8 + c4]; vv1 = v[wn * 32 + 2 * 8 + c4 + 1];
                    f = __half22float2(*(const __half2*)&ub.x);
                    rsum[mt * 2]     += f.x * vv0 + f.y * vv1;
                    f = __half22float2(*(const __half2*)&ub.y);
                    rsum[mt * 2 + 1] += f.x * vv0 + f.y * vv1;
                    vv0 = v[wn * 32 + 3 * 8 + c4]; vv1 = v[wn * 32 + 3 * 8 + c4 + 1];
                    f = __half22float2(*(const __half2*)&ub.z);
                    rsum[mt * 2]     += f.x * vv0 + f.y * vv1;
                    f = __half22float2(*(const __half2*)&ub.w);
                    rsum[mt * 2 + 1] += f.x * vv0 + f.y * vv1;
                }
            }
#pragma unroll
            for (int o = 1; o <= 2; o <<= 1)
#pragma unroll
                for (int q = 0; q < 8; q++)
                    rsum[q] += __shfl_xor_sync(0xffffffffu, rsum[q], o);
            if ((lane & 3) == 0) {
                long rowBase = (long)tile * 128 + wm * 64;
#pragma unroll
                for (int mt = 0; mt < 4; mt++) {
                    out[rowBase + mt * 16 + r4]     = rsum[mt * 2];
                    out[rowBase + mt * 16 + r4 + 8] = rsum[mt * 2 + 1];
                }
            }
        }
    }

    // ================== PHASE 2B: GEMM tiles NT1..NT_ALL-1, dot v ==================
    {
        float vc[8];
#pragma unroll
        for (int q = 0; q < 8; q++)
            vc[q] = v[warp_n * 32 + (q >> 1) * 8 + c4 + (q & 1)];
        int p = 0;
        long tile = NT1 + blockIdx.x;
        for (; tile < NT_ALL; tile += GRID_GEMM) {
            long next = tile + GRID_GEMM;
            if (next < NT_ALL) {
                prefetchA(next, Ab[p ^ 1]);
                asm volatile("cp.async.wait_group 1;");
            } else {
                asm volatile("cp.async.wait_group 0;");
            }
            __syncthreads();

            __half* As = Ab[p];
            float acc[4][4][4];
#pragma unroll
            for (int mt = 0; mt < 4; mt++)
#pragma unroll
                for (int nt = 0; nt < 4; nt++)
#pragma unroll
                    for (int q = 0; q < 4; q++) acc[mt][nt][q] = 0.f;

#pragma unroll
            for (int ks = 0; ks < 8; ks++) {
                uint32_t a[4][4];
#pragma unroll
                for (int mt = 0; mt < 4; mt++) {
                    uint32_t addr = smem_u32(As + (aRow + mt * 16) * LDA + ks * 16 + aCol);
                    ldsm_x4(a[mt][0], a[mt][1], a[mt][2], a[mt][3], addr);
                }
                uint32_t b[4][2];
#pragma unroll
                for (int np = 0; np < 2; np++) {
                    uint32_t addr = smem_u32(Bs + (warp_n * 32 + np * 16 + bRowOff) * LDB + ks * 16 + bKadd);
                    uint32_t r0, r1, r2, r3;
                    ldsm_x4(r0, r1, r2, r3, addr);
                    b[np * 2][0] = r0; b[np * 2][1] = r1;
                    b[np * 2 + 1][0] = r2; b[np * 2 + 1][1] = r3;
                }
#pragma unroll
                for (int mt = 0; mt < 4; mt++)
#pragma unroll
                    for (int nt = 0; nt < 4; nt++)
                        mma16816(acc[mt][nt], a[mt], b[nt]);
            }

            long rowBase = tile * 128;
            float rsum[8];
#pragma unroll
            for (int mt = 0; mt < 4; mt++) {
                float slo = 0.f, shi = 0.f;
#pragma unroll
                for (int nt = 0; nt < 4; nt++) {
                    float* d = acc[mt][nt];
                    float z0 = (d[0] >= 0.f) ? d[0] : pa * d[0];
                    float z1 = (d[1] >= 0.f) ? d[1] : pa * d[1];
                    float z2 = (d[2] >= 0.f) ? d[2] : pa * d[2];
                    float z3 = (d[3] >= 0.f) ? d[3] : pa * d[3];
                    slo += z0 * vc[nt * 2] + z1 * vc[nt * 2 + 1];
                    shi += z2 * vc[nt * 2] + z3 * vc[nt * 2 + 1];
                }
                rsum[mt * 2] = slo; rsum[mt * 2 + 1] = shi;
            }
#pragma unroll
            for (int o = 1; o <= 2; o <<= 1)
#pragma unroll
                for (int q = 0; q < 8; q++)
                    rsum[q] += __shfl_xor_sync(0xffffffffu, rsum[q], o);

            float* ostg = ostg0 + (int)(((tile - NT1) / GRID_GEMM) & 1) * 8 * LDO;
            if ((lane & 3) == 0) {
                float* og = ostg + warp_n * LDO + warp_m * 64;
#pragma unroll
                for (int mt = 0; mt < 4; mt++) {
                    og[mt * 16 + r4]     = rsum[mt * 2];
                    og[mt * 16 + r4 + 8] = rsum[mt * 2 + 1];
                }
            }
            __syncthreads();
            if (tid < 128) {
                long grow = rowBase + tid;
                if (grow < totalRows) {
                    float s = 0.f;
#pragma unroll
                    for (int wn = 0; wn < 8; wn++) s += ostg[wn * LDO + tid];
                    out[grow] = s;
                }
            }
            p ^= 1;
        }
    }
}

// ================= launch =================
extern "C" void kernel_launch(void* const* d_in, const int* in_sizes, int n_in,
                              void* d_out, int out_size) {
    const float* x       = (const float*)d_in[0];
    const float* x_tilde = (const float*)d_in[1];
    const float* vals    = (const float*)d_in[2];
    const int*   adj_row = (const int*)d_in[3];
    const int*   adj_col = (const int*)d_in[4];
    const float* W1      = (const float*)d_in[5];
    const float* prelu_a = (const float*)d_in[6];
    const float* w_bil   = (const float*)d_in[7];
    float* out = (float*)d_out;

    cudaFuncSetAttribute(k_gemm_all, cudaFuncAttributeMaxDynamicSharedMemorySize, SM_BYTES);

    int wblocks = (DH * DIN + 255) / 256;
    k_prep<<<ROW_BLOCKS + CVT_BLOCKS + wblocks, 256>>>(
        (const float4*)x, (const float4*)x_tilde, adj_row, W1);
    k_spmm<<<(NN * 32) / 256, 256>>>(vals, adj_col);
    k_gemm_all<<<GRID_GEMM, 512, SM_BYTES>>>(prelu_a, w_bil, out);
}

// round 16
// speedup vs baseline: 1.1456x; 1.1456x over previous
#include <cuda_runtime.h>
#include <cuda_fp16.h>
#include <math.h>
#include <stdint.h>

#define NN 100000
#define EE 1600000
#define DIN 128
#define DH  256

// ---- device scratch (allocation-free contract) ----
__device__ uint4  g_xh[(size_t)NN * 32];        // interleaved fp16 x|x_tilde [N][256]h (51.2MB)
__device__ __half g_agg16[2ull * NN * DIN];     // fp16 agg (51.2MB)
__device__ __half g_W1h[DH * DIN];              // fp16 W1 [256][128] K-major
__device__ float  g_colsum[DH];
__device__ int    g_rowptr[NN + 1];
__device__ int    g_bar;

// ================= helpers =================
__device__ __forceinline__ uint32_t smem_u32(const void* p) {
    uint32_t a;
    asm("{ .reg .u64 t; cvta.to.shared.u64 t, %1; cvt.u32.u64 %0, t; }" : "=r"(a) : "l"(p));
    return a;
}
__device__ __forceinline__ void ldsm_x4(uint32_t& r0, uint32_t& r1, uint32_t& r2, uint32_t& r3,
                                        uint32_t addr) {
    asm volatile("ldmatrix.sync.aligned.m8n8.x4.shared.b16 {%0,%1,%2,%3}, [%4];"
                 : "=r"(r0), "=r"(r1), "=r"(r2), "=r"(r3) : "r"(addr));
}
__device__ __forceinline__ void mma16816(float* d, const uint32_t* a, const uint32_t* b) {
    asm volatile("mma.sync.aligned.m16n8k16.row.col.f32.f16.f16.f32 "
                 "{%0,%1,%2,%3}, {%4,%5,%6,%7}, {%8,%9}, {%0,%1,%2,%3};"
                 : "+f"(d[0]), "+f"(d[1]), "+f"(d[2]), "+f"(d[3])
                 : "r"(a[0]), "r"(a[1]), "r"(a[2]), "r"(a[3]), "r"(b[0]), "r"(b[1]));
}
__device__ __forceinline__ void mma16816h(uint32_t* d, const uint32_t* a, const uint32_t* b) {
    asm volatile("mma.sync.aligned.m16n8k16.row.col.f16.f16.f16.f16 "
                 "{%0,%1}, {%2,%3,%4,%5}, {%6,%7}, {%0,%1};"
                 : "+r"(d[0]), "+r"(d[1])
                 : "r"(a[0]), "r"(a[1]), "r"(a[2]), "r"(a[3]), "r"(b[0]), "r"(b[1]));
}
__device__ __forceinline__ uint32_t prelu2(uint32_t z, __half2 pa2) {
    __half2 h = *(__half2*)&z;
    __half2 zero = __half2half2(__ushort_as_half(0));
    __half2 r = __hfma2(__hmin2(h, zero), pa2, __hmax2(h, zero));
    return *(uint32_t*)&r;
}
__device__ __forceinline__ void cp_async16(uint32_t saddr, const void* gptr, int src_bytes) {
    uint64_t ga;
    asm("cvta.to.global.u64 %0, %1;" : "=l"(ga) : "l"(gptr));
    asm volatile("cp.async.cg.shared.global [%0], [%1], 16, %2;"
                 :: "r"(saddr), "l"(ga), "r"(src_bytes));
}
__device__ __forceinline__ void cp_commit() {
    asm volatile("cp.async.commit_group;");
}
__device__ __forceinline__ void stg_cs_v4(void* gptr, uint4 v) {
    asm volatile("st.global.cs.v4.b32 [%0], {%1, %2, %3, %4};"
                 :: "l"(gptr), "r"(v.x), "r"(v.y), "r"(v.z), "r"(v.w) : "memory");
}

// ================= fused prep: rowptr | cvt | cvtW+init (rowptr first for tail overlap) =================
#define ROW_BLOCKS 6250
#define CVT_BLOCKS 12500
__global__ void k_prep(const float4* __restrict__ x4, const float4* __restrict__ xt4,
                       const int* __restrict__ adj_row, const float* __restrict__ W1) {
    int b = blockIdx.x, t = threadIdx.x;
    if (b < ROW_BLOCKS) {
        int e = b * 256 + t;
        if (e >= EE) return;
        int r  = adj_row[e];
        int rp = (e == 0) ? -1 : adj_row[e - 1];
        for (int k = rp + 1; k <= r; k++) g_rowptr[k] = e;
        if (e == EE - 1)
            for (int k = r + 1; k <= NN; k++) g_rowptr[k] = EE;
    } else if (b < ROW_BLOCKS + CVT_BLOCKS) {
        int i = (b - ROW_BLOCKS) * 256 + t;
        if (i >= NN * 32) return;
        int row = i >> 5, j = i & 31;
        const float4* src = (j < 16) ? x4 : xt4;
        int jj = j & 15;
        float4 a = src[(size_t)row * 32 + jj * 2];
        float4 c = src[(size_t)row * 32 + jj * 2 + 1];
        __half2 h0 = __floats2half2_rn(a.x, a.y);
        __half2 h1 = __floats2half2_rn(a.z, a.w);
        __half2 h2 = __floats2half2_rn(c.x, c.y);
        __half2 h3 = __floats2half2_rn(c.z, c.w);
        uint4 o;
        o.x = *(unsigned*)&h0; o.y = *(unsigned*)&h1;
        o.z = *(unsigned*)&h2; o.w = *(unsigned*)&h3;
        g_xh[(size_t)row * 32 + j] = o;
    } else {
        int wb = b - ROW_BLOCKS - CVT_BLOCKS;
        int i = wb * 256 + t;
        if (i < DH * DIN) g_W1h[i] = __float2half_rn(W1[i]);
        if (wb == 0) {
            g_colsum[t] = 0.0f;
            if (t == 0) g_bar = 0;
        }
    }
}

// ================= SpMM (fp16 gather, fp16 agg out, streaming stores) =================
__global__ void k_spmm(const float* __restrict__ vals, const int* __restrict__ cols) {
    int w    = (blockIdx.x * blockDim.x + threadIdx.x) >> 5;
    int lane = threadIdx.x & 31;
    if (w >= NN) return;
    int e0 = g_rowptr[w], e1 = g_rowptr[w + 1];
    float a0 = 0.f, a1 = 0.f, a2 = 0.f, a3 = 0.f, a4 = 0.f, a5 = 0.f, a6 = 0.f, a7 = 0.f;
#pragma unroll 4
    for (int e = e0; e < e1; e++) {
        float wt = __ldg(vals + e);
        int   c  = __ldg(cols + e);
        uint4 u  = g_xh[(size_t)c * 32 + lane];
        float2 f0 = __half22float2(*(const __half2*)&u.x);
        float2 f1 = __half22float2(*(const __half2*)&u.y);
        float2 f2 = __half22float2(*(const __half2*)&u.z);
        float2 f3 = __half22float2(*(const __half2*)&u.w);
        a0 += wt * f0.x; a1 += wt * f0.y;
        a2 += wt * f1.x; a3 += wt * f1.y;
        a4 += wt * f2.x; a5 += wt * f2.y;
        a6 += wt * f3.x; a7 += wt * f3.y;
    }
    size_t base = (lane < 16) ? (size_t)w : (size_t)NN + w;
    int j = lane & 15;
    __half2 h0 = __floats2half2_rn(a0, a1);
    __half2 h1 = __floats2half2_rn(a2, a3);
    __half2 h2 = __floats2half2_rn(a4, a5);
    __half2 h3 = __floats2half2_rn(a6, a7);
    uint4 o;
    o.x = *(unsigned*)&h0; o.y = *(unsigned*)&h1;
    o.z = *(unsigned*)&h2; o.w = *(unsigned*)&h3;
    stg_cs_v4((uint4*)g_agg16 + base * 16 + j, o);
}

// ================= single persistent GEMM kernel =================
// 512 thr = 16 warps (2x8), warp tile 64x32. GRID = 152 (GB300 SM count).
// PASS1 (fp16 acc): rows<NN -> colsum.  Grid barrier.  s,v per CTA.
// PASS2 (fp32 acc): all 2N rows -> out[row] = PReLU(z) . v
#define LDA 136
#define LDB 136
#define ASZ (128 * LDA)
#define SM_HALVES (2 * ASZ + 256 * LDB)
#define LDO 132
#define SM_BYTES (SM_HALVES * 2 + 2 * 8 * LDO * 4 + 2048)
#define GRID_GEMM 152

__global__ void __launch_bounds__(512, 1) k_gemm_all(const float* __restrict__ prelu_a,
                                                     const float* __restrict__ w_bil,
                                                     float* __restrict__ out) {
    extern __shared__ __half smem[];
    __half* Ab[2] = { smem, smem + ASZ };
    __half* Bs = smem + 2 * ASZ;                  // [256][LDB]
    float* ostg0 = (float*)(smem + SM_HALVES);    // [8][LDO] x 2 (double buffer)
    float* sv   = ostg0 + 2 * 8 * LDO;            // s[256] then v[256]
    int tid = threadIdx.x, lane = tid & 31, wid = tid >> 5;
    int warp_m = wid >> 3, warp_n = wid & 7;      // 2 x 8
    const long totalRows = 2L * NN;

    // ---- load B (all of W1h) once ----
    {
        const uint4* bsrc = (const uint4*)g_W1h;
#pragma unroll
        for (int i = 0; i < 8; i++) {
            int c = tid + i * 512;
            int row = c >> 4, k4 = c & 15;
            *(uint4*)(Bs + row * LDB + k4 * 8) = bsrc[row * 16 + k4];
        }
    }

    auto prefetchA = [&](long tile, __half* dst) {
        const uint4* asrc = (const uint4*)g_agg16;
        long rb = tile * 128;
#pragma unroll
        for (int i = 0; i < 4; i++) {
            int c = tid + i * 512;
            int row = c >> 4, k4 = c & 15;
            long grow = rb + row;
            int ok = (grow < totalRows) ? 16 : 0;
            long src = ok ? grow : 0;
            cp_async16(smem_u32(dst + row * LDA + k4 * 8), asrc + src * 16 + k4, ok);
        }
        cp_commit();
    };

    float pa = prelu_a[0];
    __half2 pa2 = __float2half2_rn(pa);
    int r4 = lane >> 2, c4 = (lane & 3) * 2;
    int aRow = warp_m * 64 + (lane & 15);
    int aCol = (lane >> 4) * 8;
    int bGrp = lane >> 3;
    int bRowOff = ((bGrp >> 1) * 8) + (lane & 7);
    int bKadd = (bGrp & 1) * 8;

    // ================== PASS 1: colsum (fp16 acc) ==================
    {
        const long nt1 = (NN + 127) / 128;
        uint32_t csum2[4] = {0u, 0u, 0u, 0u};
        int p = 0;
        long tile = blockIdx.x;
        if (tile < nt1) prefetchA(tile, Ab[0]);
        for (; tile < nt1; tile += GRID_GEMM) {
            long next = tile + GRID_GEMM;
            if (next < nt1) {
                prefetchA(next, Ab[p ^ 1]);
                asm volatile("cp.async.wait_group 1;");
            } else {
                asm volatile("cp.async.wait_group 0;");
            }
            __syncthreads();

            __half* As = Ab[p];
            uint32_t acc[4][4][2];
#pragma unroll
            for (int mt = 0; mt < 4; mt++)
#pragma unroll
                for (int nt = 0; nt < 4; nt++) { acc[mt][nt][0] = 0u; acc[mt][nt][1] = 0u; }

#pragma unroll
            for (int ks = 0; ks < 8; ks++) {
                uint32_t a[4][4];
#pragma unroll
                for (int mt = 0; mt < 4; mt++) {
                    uint32_t addr = smem_u32(As + (aRow + mt * 16) * LDA + ks * 16 + aCol);
                    ldsm_x4(a[mt][0], a[mt][1], a[mt][2], a[mt][3], addr);
                }
                uint32_t b[4][2];
#pragma unroll
                for (int np = 0; np < 2; np++) {
                    uint32_t addr = smem_u32(Bs + (warp_n * 32 + np * 16 + bRowOff) * LDB + ks * 16 + bKadd);
                    uint32_t r0, r1, r2, r3;
                    ldsm_x4(r0, r1, r2, r3, addr);
                    b[np * 2][0] = r0; b[np * 2][1] = r1;
                    b[np * 2 + 1][0] = r2; b[np * 2 + 1][1] = r3;
                }
#pragma unroll
                for (int mt = 0; mt < 4; mt++)
#pragma unroll
                    for (int nt = 0; nt < 4; nt++)
                        mma16816h(acc[mt][nt], a[mt], b[nt]);
            }

            long rowBase = tile * 128;
#pragma unroll
            for (int mt = 0; mt < 4; mt++) {
                long r_lo = rowBase + warp_m * 64 + mt * 16 + r4;
                bool p_lo = r_lo < NN, p_hi = (r_lo + 8) < NN;
#pragma unroll
                for (int nt = 0; nt < 4; nt++) {
                    uint32_t z0 = prelu2(acc[mt][nt][0], pa2);
                    uint32_t z1 = prelu2(acc[mt][nt][1], pa2);
                    __half2 c = *(__half2*)&csum2[nt];
                    if (p_lo) c = __hadd2(c, *(__half2*)&z0);
                    if (p_hi) c = __hadd2(c, *(__half2*)&z1);
                    csum2[nt] = *(uint32_t*)&c;
                }
            }
            __syncthreads();
            p ^= 1;
        }
#pragma unroll
        for (int o = 4; o <= 16; o <<= 1)
#pragma unroll
            for (int nt = 0; nt < 4; nt++) {
                uint32_t other = __shfl_xor_sync(0xffffffffu, csum2[nt], o);
                __half2 c = __hadd2(*(__half2*)&csum2[nt], *(__half2*)&other);
                csum2[nt] = *(uint32_t*)&c;
            }
        if (lane < 4) {
#pragma unroll
            for (int nt = 0; nt < 4; nt++) {
                float2 f = __half22float2(*(__half2*)&csum2[nt]);
                atomicAdd(&g_colsum[warp_n * 32 + nt * 8 + lane * 2],     f.x);
                atomicAdd(&g_colsum[warp_n * 32 + nt * 8 + lane * 2 + 1], f.y);
            }
        }
    }

    // ================== grid-wide barrier ==================
    __threadfence();
    __syncthreads();
    if (tid == 0) {
        atomicAdd(&g_bar, 1);
        while (*(volatile int*)&g_bar < GRID_GEMM) { }
    }
    __syncthreads();
    __threadfence();

    // ================== s = sigmoid(colsum/N), v = w_bil @ s ==================
    {
        const long nt2 = (2 * NN + 127) / 128;
        if (blockIdx.x < nt2) prefetchA(blockIdx.x, Ab[0]);   // overlap with v compute
        if (tid < 256) {
            float m = g_colsum[tid] / (float)NN;
            sv[tid] = 1.f / (1.f + expf(-m));
        }
        __syncthreads();
        int j0 = wid * 16;
#pragma unroll 2
        for (int jj = 0; jj < 16; jj++) {
            int j = j0 + jj;
            float a = 0.f;
#pragma unroll
            for (int u = 0; u < 8; u++)
                a += __ldg(&w_bil[j * DH + lane + u * 32]) * sv[lane + u * 32];
#pragma unroll
            for (int o = 16; o > 0; o >>= 1) a += __shfl_xor_sync(0xffffffffu, a, o);
            if (lane == 0) sv[DH + j] = a;
        }
        __syncthreads();
    }
    float* v = sv + DH;
    float vc[8];
#pragma unroll
    for (int q = 0; q < 8; q++)
        vc[q] = v[warp_n * 32 + (q >> 1) * 8 + c4 + (q & 1)];

    // ================== PASS 2: out = PReLU(z) . v (fp32 acc) ==================
    {
        const long nt2 = (2 * NN + 127) / 128;
        int p = 0;
        long tile = blockIdx.x;
        for (; tile < nt2; tile += GRID_GEMM) {
            long next = tile + GRID_GEMM;
            if (next < nt2) {
                prefetchA(next, Ab[p ^ 1]);
                asm volatile("cp.async.wait_group 1;");
            } else {
                asm volatile("cp.async.wait_group 0;");
            }
            __syncthreads();

            __half* As = Ab[p];
            float acc[4][4][4];
#pragma unroll
            for (int mt = 0; mt < 4; mt++)
#pragma unroll
                for (int nt = 0; nt < 4; nt++)
#pragma unroll
                    for (int q = 0; q < 4; q++) acc[mt][nt][q] = 0.f;

#pragma unroll
            for (int ks = 0; ks < 8; ks++) {
                uint32_t a[4][4];
#pragma unroll
                for (int mt = 0; mt < 4; mt++) {
                    uint32_t addr = smem_u32(As + (aRow + mt * 16) * LDA + ks * 16 + aCol);
                    ldsm_x4(a[mt][0], a[mt][1], a[mt][2], a[mt][3], addr);
                }
                uint32_t b[4][2];
#pragma unroll
                for (int np = 0; np < 2; np++) {
                    uint32_t addr = smem_u32(Bs + (warp_n * 32 + np * 16 + bRowOff) * LDB + ks * 16 + bKadd);
                    uint32_t r0, r1, r2, r3;
                    ldsm_x4(r0, r1, r2, r3, addr);
                    b[np * 2][0] = r0; b[np * 2][1] = r1;
                    b[np * 2 + 1][0] = r2; b[np * 2 + 1][1] = r3;
                }
#pragma unroll
                for (int mt = 0; mt < 4; mt++)
#pragma unroll
                    for (int nt = 0; nt < 4; nt++)
                        mma16816(acc[mt][nt], a[mt], b[nt]);
            }

            long rowBase = tile * 128;
            float rsum[8];
#pragma unroll
            for (int mt = 0; mt < 4; mt++) {
                float slo = 0.f, shi = 0.f;
#pragma unroll
                for (int nt = 0; nt < 4; nt++) {
                    float* d = acc[mt][nt];
                    float z0 = (d[0] >= 0.f) ? d[0] : pa * d[0];
                    float z1 = (d[1] >= 0.f) ? d[1] : pa * d[1];
                    float z2 = (d[2] >= 0.f) ? d[2] : pa * d[2];
                    float z3 = (d[3] >= 0.f) ? d[3] : pa * d[3];
                    slo += z0 * vc[nt * 2] + z1 * vc[nt * 2 + 1];
                    shi += z2 * vc[nt * 2] + z3 * vc[nt * 2 + 1];
                }
                rsum[mt * 2] = slo; rsum[mt * 2 + 1] = shi;
            }
#pragma unroll
            for (int o = 1; o <= 2; o <<= 1)
#pragma unroll
                for (int q = 0; q < 8; q++)
                    rsum[q] += __shfl_xor_sync(0xffffffffu, rsum[q], o);

            // non-atomic staging, double-buffered: no trailing sync needed
            float* ostg = ostg0 + (int)((tile / GRID_GEMM) & 1) * 8 * LDO;
            if ((lane & 3) == 0) {
                float* og = ostg + warp_n * LDO + warp_m * 64;
#pragma unroll
                for (int mt = 0; mt < 4; mt++) {
                    og[mt * 16 + r4]     = rsum[mt * 2];
                    og[mt * 16 + r4 + 8] = rsum[mt * 2 + 1];
                }
            }
            __syncthreads();
            if (tid < 128) {
                long grow = rowBase + tid;
                if (grow < totalRows) {
                    float s = 0.f;
#pragma unroll
                    for (int wn = 0; wn < 8; wn++) s += ostg[wn * LDO + tid];
                    out[grow] = s;
                }
            }
            p ^= 1;
        }
    }
}

// ================= launch =================
extern "C" void kernel_launch(void* const* d_in, const int* in_sizes, int n_in,
                              void* d_out, int out_size) {
    const float* x       = (const float*)d_in[0];
    const float* x_tilde = (const float*)d_in[1];
    const float* vals    = (const float*)d_in[2];
    const int*   adj_row = (const int*)d_in[3];
    const int*   adj_col = (const int*)d_in[4];
    const float* W1      = (const float*)d_in[5];
    const float* prelu_a = (const float*)d_in[6];
    const float* w_bil   = (const float*)d_in[7];
    float* out = (float*)d_out;

    cudaFuncSetAttribute(k_gemm_all, cudaFuncAttributeMaxDynamicSharedMemorySize, SM_BYTES);

    int wblocks = (DH * DIN + 255) / 256;
    k_prep<<<ROW_BLOCKS + CVT_BLOCKS + wblocks, 256>>>(
        (const float4*)x, (const float4*)x_tilde, adj_row, W1);
    k_spmm<<<(NN * 32) / 256, 256>>>(vals, adj_col);
    k_gemm_all<<<GRID_GEMM, 512, SM_BYTES>>>(prelu_a, w_bil, out);
}